// round 1
// baseline (speedup 1.0000x reference)
#include <cuda_runtime.h>
#include <math.h>

// Problem constants
static constexpr int B_   = 64;
static constexpr int HENC = 512;
static constexpr int E_   = 512;
static constexpr int H_   = 1024;
static constexpr int V_   = 32000;
static constexpr int T_   = 64;
static constexpr int SOS  = 1;
static constexpr int EOS  = 2;

// Persistent device state (no allocations allowed)
__device__ float g_flat[B_ * 2 * HENC];         // context / flattened encoder hidden
__device__ float g_h[B_ * H_];                  // GRU hidden state
__device__ float g_Gc[B_ * 3 * H_];             // constant context part of gi (incl b_ih)
__device__ float g_gi[B_ * 3 * H_];
__device__ float g_gh[B_ * 3 * H_];
__device__ int   g_inp[B_];
__device__ int   g_fin[B_];
__device__ unsigned long long g_amax[B_];       // packed (ordered-float << 32 | ~col)

// ---------------------------------------------------------------------------
// Setup: build flat = transpose(encoder_hidden) reshape, init token state
// ---------------------------------------------------------------------------
__global__ void k_setup(const float* __restrict__ enc) {
    int idx = blockIdx.x * blockDim.x + threadIdx.x;
    if (idx < B_ * 2 * HENC) {
        int b = idx / (2 * HENC);
        int k = idx % (2 * HENC);
        float v = (k < HENC) ? enc[b * HENC + k]
                             : enc[B_ * HENC + b * HENC + (k - HENC)];
        g_flat[idx] = v;
    }
    if (idx < B_) { g_inp[idx] = SOS; g_fin[idx] = 0; }
}

// ---------------------------------------------------------------------------
// Generic fp32 GEMM: C[64, N] = A[64, K] @ W[N, K]^T (+bias) (+addend)
// A rows optionally gathered (embedding lookup). M = 64 fixed (one tile row).
// Tile: 64x64, BK=32, 256 threads, 4x4 per thread.
// ---------------------------------------------------------------------------
__global__ void __launch_bounds__(256) k_gemm(
    const float* __restrict__ A, int lda, const int* __restrict__ gather,
    const float* __restrict__ W, int ldw, int woff, int K,
    const float* __restrict__ bias, const float* __restrict__ addend,
    float* __restrict__ C, int ldc)
{
    __shared__ float As[32][68];
    __shared__ float Ws[32][68];
    const int tid = threadIdx.x;
    const int tx = tid & 15, ty = tid >> 4;
    const int n0 = blockIdx.x * 64;
    float acc[4][4] = {};

    for (int k0 = 0; k0 < K; k0 += 32) {
#pragma unroll
        for (int it = 0; it < 2; it++) {
            int idx = tid + it * 256;      // 0..511
            int row = idx >> 3;            // 0..63
            int kq  = (idx & 7) << 2;      // 0,4,..,28
            const float* ap = gather ? (A + (size_t)gather[row] * lda + k0 + kq)
                                     : (A + (size_t)row * lda + k0 + kq);
            float4 v = *(const float4*)ap;
            As[kq][row] = v.x; As[kq + 1][row] = v.y;
            As[kq + 2][row] = v.z; As[kq + 3][row] = v.w;
            const float* wp = W + (size_t)(n0 + row) * ldw + woff + k0 + kq;
            float4 u = *(const float4*)wp;
            Ws[kq][row] = u.x; Ws[kq + 1][row] = u.y;
            Ws[kq + 2][row] = u.z; Ws[kq + 3][row] = u.w;
        }
        __syncthreads();
#pragma unroll
        for (int k = 0; k < 32; k++) {
            float4 a = *(const float4*)&As[k][ty << 2];
            float4 w = *(const float4*)&Ws[k][tx << 2];
            acc[0][0] += a.x * w.x; acc[0][1] += a.x * w.y; acc[0][2] += a.x * w.z; acc[0][3] += a.x * w.w;
            acc[1][0] += a.y * w.x; acc[1][1] += a.y * w.y; acc[1][2] += a.y * w.z; acc[1][3] += a.y * w.w;
            acc[2][0] += a.z * w.x; acc[2][1] += a.z * w.y; acc[2][2] += a.z * w.z; acc[2][3] += a.z * w.w;
            acc[3][0] += a.w * w.x; acc[3][1] += a.w * w.y; acc[3][2] += a.w * w.z; acc[3][3] += a.w * w.w;
        }
        __syncthreads();
    }
#pragma unroll
    for (int i = 0; i < 4; i++) {
        int row = (ty << 2) + i;
#pragma unroll
        for (int j = 0; j < 4; j++) {
            int col = n0 + (tx << 2) + j;
            float v = acc[i][j];
            if (bias)   v += bias[col];
            if (addend) v += addend[(size_t)row * ldc + col];
            C[(size_t)row * ldc + col] = v;
        }
    }
}

// ---------------------------------------------------------------------------
// Vocab projection with FUSED argmax. Logits never hit memory.
// key = (ordered_float_bits << 32) | (0xFFFFFFFF - col)  -> max key == argmax,
// ties resolve to lowest col (JAX argmax semantics).
// ---------------------------------------------------------------------------
__global__ void __launch_bounds__(256) k_logits(
    const float* __restrict__ Wo, const float* __restrict__ bo)
{
    __shared__ float As[32][68];
    __shared__ float Ws[32][68];
    __shared__ unsigned long long sm[64];
    const int tid = threadIdx.x;
    const int tx = tid & 15, ty = tid >> 4;
    const int n0 = blockIdx.x * 64;
    if (tid < 64) sm[tid] = 0ULL;
    float acc[4][4] = {};

    for (int k0 = 0; k0 < H_; k0 += 32) {
#pragma unroll
        for (int it = 0; it < 2; it++) {
            int idx = tid + it * 256;
            int row = idx >> 3;
            int kq  = (idx & 7) << 2;
            float4 v = *(const float4*)(g_h + (size_t)row * H_ + k0 + kq);
            As[kq][row] = v.x; As[kq + 1][row] = v.y;
            As[kq + 2][row] = v.z; As[kq + 3][row] = v.w;
            float4 u = *(const float4*)(Wo + (size_t)(n0 + row) * H_ + k0 + kq);
            Ws[kq][row] = u.x; Ws[kq + 1][row] = u.y;
            Ws[kq + 2][row] = u.z; Ws[kq + 3][row] = u.w;
        }
        __syncthreads();
#pragma unroll
        for (int k = 0; k < 32; k++) {
            float4 a = *(const float4*)&As[k][ty << 2];
            float4 w = *(const float4*)&Ws[k][tx << 2];
            acc[0][0] += a.x * w.x; acc[0][1] += a.x * w.y; acc[0][2] += a.x * w.z; acc[0][3] += a.x * w.w;
            acc[1][0] += a.y * w.x; acc[1][1] += a.y * w.y; acc[1][2] += a.y * w.z; acc[1][3] += a.y * w.w;
            acc[2][0] += a.z * w.x; acc[2][1] += a.z * w.y; acc[2][2] += a.z * w.z; acc[2][3] += a.z * w.w;
            acc[3][0] += a.w * w.x; acc[3][1] += a.w * w.y; acc[3][2] += a.w * w.z; acc[3][3] += a.w * w.w;
        }
        __syncthreads();
    }
#pragma unroll
    for (int i = 0; i < 4; i++) {
        int row = (ty << 2) + i;
        float best = 0.f; int bc = 0;
#pragma unroll
        for (int j = 0; j < 4; j++) {
            float v = acc[i][j] + bo[n0 + (tx << 2) + j];
            if (j == 0 || v > best) { best = v; bc = j; }
        }
        unsigned ub = __float_as_uint(best);
        ub = (ub & 0x80000000u) ? ~ub : (ub | 0x80000000u);
        unsigned col = (unsigned)(n0 + (tx << 2) + bc);
        unsigned long long key = ((unsigned long long)ub << 32) | (0xFFFFFFFFu - col);
        atomicMax(&sm[row], key);
    }
    __syncthreads();
    if (tid < 64) atomicMax(&g_amax[tid], sm[tid]);
}

// ---------------------------------------------------------------------------
// GRU gate nonlinearity + hidden update; also resets argmax slots for this step
// ---------------------------------------------------------------------------
__global__ void k_gates() {
    int idx = blockIdx.x * blockDim.x + threadIdx.x;
    if (blockIdx.x == 0 && threadIdx.x < B_) g_amax[threadIdx.x] = 0ULL;
    if (idx >= B_ * H_) return;
    int b = idx / H_, i = idx % H_;
    const float* gi = g_gi + (size_t)b * 3 * H_;
    const float* gh = g_gh + (size_t)b * 3 * H_;
    float r = 1.f / (1.f + expf(-(gi[i] + gh[i])));
    float z = 1.f / (1.f + expf(-(gi[H_ + i] + gh[H_ + i])));
    float n = tanhf(gi[2 * H_ + i] + r * gh[2 * H_ + i]);
    float h = g_h[idx];
    g_h[idx] = (1.f - z) * n + z * h;
}

// ---------------------------------------------------------------------------
// Decode argmax -> token, finished/eos masking, record token as float
// ---------------------------------------------------------------------------
__global__ void k_token(float* __restrict__ out_tok, int t) {
    int b = threadIdx.x;
    if (b >= B_) return;
    unsigned long long key = g_amax[b];
    int tok = (int)(0xFFFFFFFFu - (unsigned)(key & 0xFFFFFFFFull));
    out_tok[b * T_ + t] = (float)tok;
    int fin = g_fin[b] | (tok == EOS);
    g_fin[b] = fin;
    g_inp[b] = fin ? EOS : tok;
}

__global__ void k_writeh(float* __restrict__ out_h) {
    int idx = blockIdx.x * blockDim.x + threadIdx.x;
    if (idx < B_ * H_) out_h[idx] = g_h[idx];
}

// ---------------------------------------------------------------------------
extern "C" void kernel_launch(void* const* d_in, const int* in_sizes, int n_in,
                              void* d_out, int out_size) {
    const float* enc   = (const float*)d_in[0];
    const float* emb   = (const float*)d_in[1];
    const float* Wh_w  = (const float*)d_in[2];
    const float* Wh_b  = (const float*)d_in[3];
    const float* W_ih  = (const float*)d_in[4];
    const float* W_hh  = (const float*)d_in[5];
    const float* b_ih  = (const float*)d_in[6];
    const float* b_hh  = (const float*)d_in[7];
    const float* out_w = (const float*)d_in[8];
    const float* out_b = (const float*)d_in[9];
    float* out = (float*)d_out;

    // Device-symbol addresses (host API, not a stream op: capture-safe)
    void *p_flat, *p_h, *p_Gc, *p_gi, *p_gh, *p_inp;
    cudaGetSymbolAddress(&p_flat, g_flat);
    cudaGetSymbolAddress(&p_h,    g_h);
    cudaGetSymbolAddress(&p_Gc,   g_Gc);
    cudaGetSymbolAddress(&p_gi,   g_gi);
    cudaGetSymbolAddress(&p_gh,   g_gh);
    cudaGetSymbolAddress(&p_inp,  g_inp);
    float* f_flat = (float*)p_flat;
    float* f_h    = (float*)p_h;
    float* f_Gc   = (float*)p_Gc;
    float* f_gi   = (float*)p_gi;
    float* f_gh   = (float*)p_gh;
    int*   i_inp  = (int*)p_inp;

    // Setup: flat/context, h0, constant context gate contribution
    k_setup<<<256, 256>>>(enc);
    // h0 = flat @ Wh_w^T + Wh_b          [64,1024] x [1024,1024]
    k_gemm<<<H_ / 64, 256>>>(f_flat, 2 * HENC, nullptr,
                             Wh_w, 2 * HENC, 0, 2 * HENC,
                             Wh_b, nullptr, f_h, H_);
    // Gc = context @ W_ih[:,E:]^T + b_ih [64,1024] x [3072,1024]
    k_gemm<<<3 * H_ / 64, 256>>>(f_flat, 2 * HENC, nullptr,
                                 W_ih, E_ + 2 * HENC, E_, 2 * HENC,
                                 b_ih, nullptr, f_Gc, 3 * H_);

    for (int t = 0; t < T_; t++) {
        // gi = emb[inp] @ W_ih[:,:E]^T + Gc    (K=512, gathered A)
        k_gemm<<<3 * H_ / 64, 256>>>(emb, E_, i_inp,
                                     W_ih, E_ + 2 * HENC, 0, E_,
                                     nullptr, f_Gc, f_gi, 3 * H_);
        // gh = h @ W_hh^T + b_hh               (K=1024)
        k_gemm<<<3 * H_ / 64, 256>>>(f_h, H_, nullptr,
                                     W_hh, H_, 0, H_,
                                     b_hh, nullptr, f_gh, 3 * H_);
        k_gates<<<(B_ * H_ + 255) / 256, 256>>>();
        k_logits<<<V_ / 64, 256>>>(out_w, out_b);
        k_token<<<1, 64>>>(out, t);
    }

    if (out_size >= B_ * T_ + B_ * H_)
        k_writeh<<<(B_ * H_ + 255) / 256, 256>>>(out + B_ * T_);
}

// round 3
// speedup vs baseline: 1.1588x; 1.1588x over previous
#include <cuda_runtime.h>
#include <cuda_bf16.h>
#include <math.h>
#include <stdint.h>

static constexpr int B_   = 64;
static constexpr int HENC = 512;
static constexpr int E_   = 512;
static constexpr int H_   = 1024;
static constexpr int V_   = 32000;
static constexpr int T_   = 64;
static constexpr int SOS  = 1;
static constexpr int EOS  = 2;

// ---------------- persistent device state ----------------
__device__ float g_flat[B_ * 2 * HENC];
__device__ float g_h[B_ * H_];
__device__ float g_Gc[B_ * 3 * H_];          // context part of gi (incl b_ih), [64][3072]
__device__ float g_giT[3 * H_ * B_];         // [3072][64]
__device__ float g_ghT[3 * H_ * B_];
__device__ int   g_inp[B_];
__device__ int   g_fin[B_];
__device__ unsigned long long g_amax[B_];

// bf16 split weights / activations
__device__ __nv_bfloat16 g_WihE_hi[3 * H_ * E_];
__device__ __nv_bfloat16 g_WihE_lo[3 * H_ * E_];
__device__ __nv_bfloat16 g_Whh_hi[3 * H_ * H_];
__device__ __nv_bfloat16 g_Whh_lo[3 * H_ * H_];
__device__ __nv_bfloat16 g_Wout_hi[(size_t)V_ * H_];
__device__ __nv_bfloat16 g_Wout_lo[(size_t)V_ * H_];
__device__ __nv_bfloat16 g_x_hi[B_ * E_];
__device__ __nv_bfloat16 g_x_lo[B_ * E_];
__device__ __nv_bfloat16 g_h_hi[B_ * H_];
__device__ __nv_bfloat16 g_h_lo[B_ * H_];

// ---------------------------------------------------------------------------
__global__ void k_setup(const float* __restrict__ enc) {
    int idx = blockIdx.x * blockDim.x + threadIdx.x;
    if (idx < B_ * 2 * HENC) {
        int b = idx / (2 * HENC);
        int k = idx % (2 * HENC);
        float v = (k < HENC) ? enc[b * HENC + k]
                             : enc[B_ * HENC + b * HENC + (k - HENC)];
        g_flat[idx] = v;
    }
    if (idx < B_) { g_inp[idx] = SOS; g_fin[idx] = 0; }
}

// ---------------------------------------------------------------------------
// fp32 GEMM (one-time use: h0 and Gc). C[64,N] = A[64,K] @ W[N,K]^T + bias
// ---------------------------------------------------------------------------
__global__ void __launch_bounds__(256) k_gemm(
    const float* __restrict__ A, int lda,
    const float* __restrict__ W, int ldw, int woff, int K,
    const float* __restrict__ bias, float* __restrict__ C, int ldc)
{
    __shared__ float As[32][68];
    __shared__ float Ws[32][68];
    const int tid = threadIdx.x;
    const int tx = tid & 15, ty = tid >> 4;
    const int n0 = blockIdx.x * 64;
    float acc[4][4] = {};

    for (int k0 = 0; k0 < K; k0 += 32) {
#pragma unroll
        for (int it = 0; it < 2; it++) {
            int idx = tid + it * 256;
            int row = idx >> 3;
            int kq  = (idx & 7) << 2;
            float4 v = *(const float4*)(A + (size_t)row * lda + k0 + kq);
            As[kq][row] = v.x; As[kq + 1][row] = v.y;
            As[kq + 2][row] = v.z; As[kq + 3][row] = v.w;
            float4 u = *(const float4*)(W + (size_t)(n0 + row) * ldw + woff + k0 + kq);
            Ws[kq][row] = u.x; Ws[kq + 1][row] = u.y;
            Ws[kq + 2][row] = u.z; Ws[kq + 3][row] = u.w;
        }
        __syncthreads();
#pragma unroll
        for (int k = 0; k < 32; k++) {
            float4 a = *(const float4*)&As[k][ty << 2];
            float4 w = *(const float4*)&Ws[k][tx << 2];
            acc[0][0] += a.x * w.x; acc[0][1] += a.x * w.y; acc[0][2] += a.x * w.z; acc[0][3] += a.x * w.w;
            acc[1][0] += a.y * w.x; acc[1][1] += a.y * w.y; acc[1][2] += a.y * w.z; acc[1][3] += a.y * w.w;
            acc[2][0] += a.z * w.x; acc[2][1] += a.z * w.y; acc[2][2] += a.z * w.z; acc[2][3] += a.z * w.w;
            acc[3][0] += a.w * w.x; acc[3][1] += a.w * w.y; acc[3][2] += a.w * w.z; acc[3][3] += a.w * w.w;
        }
        __syncthreads();
    }
#pragma unroll
    for (int i = 0; i < 4; i++) {
        int row = (ty << 2) + i;
#pragma unroll
        for (int j = 0; j < 4; j++) {
            int col = n0 + (tx << 2) + j;
            float v = acc[i][j];
            if (bias) v += bias[col];
            C[(size_t)row * ldc + col] = v;
        }
    }
}

// ---------------------------------------------------------------------------
// weight split: fp32 [rows][ld] (col offset) -> packed bf16 hi/lo [rows][cols]
// ---------------------------------------------------------------------------
__global__ void k_splitw(const float* __restrict__ src, int ld, int coloff, int cols,
                         __nv_bfloat16* __restrict__ hi, __nv_bfloat16* __restrict__ lo,
                         int n)
{
    int idx = blockIdx.x * blockDim.x + threadIdx.x;
    if (idx >= n) return;
    int r = idx / cols, c = idx % cols;
    float v = src[(size_t)r * ld + coloff + c];
    __nv_bfloat16 h = __float2bfloat16(v);
    hi[idx] = h;
    lo[idx] = __float2bfloat16(v - __bfloat162float(h));
}

// split current h (fp32) into bf16 hi/lo (used once for h0)
__global__ void k_split_h0() {
    int idx = blockIdx.x * blockDim.x + threadIdx.x;
    if (idx >= B_ * H_) return;
    float v = g_h[idx];
    __nv_bfloat16 h = __float2bfloat16(v);
    g_h_hi[idx] = h;
    g_h_lo[idx] = __float2bfloat16(v - __bfloat162float(h));
}

// gather embedding of current tokens + split; also resets argmax slots
__global__ void k_split_x(const float* __restrict__ emb) {
    int idx = blockIdx.x * blockDim.x + threadIdx.x;
    if (idx < B_) g_amax[idx] = 0ULL;
    if (idx >= B_ * E_) return;
    int b = idx >> 9;
    int k = idx & (E_ - 1);
    float v = emb[(size_t)g_inp[b] * E_ + k];
    __nv_bfloat16 h = __float2bfloat16(v);
    g_x_hi[idx] = h;
    g_x_lo[idx] = __float2bfloat16(v - __bfloat162float(h));
}

// ---------------------------------------------------------------------------
// Tensor-core split-bf16 GEMM:  D[M,64] = (Ah+Al)[M,K] @ (Bh+Bl)[64,K]^T
// (3 products: AhBh + AhBl + AlBh).  Optional bias[m], addend[n][m] (ld=ald).
// do_argmax: fused per-batch argmax over m into g_amax (logits path).
// Tile: 128 x 64, 8 warps, mma.m16n8k16.bf16, ldmatrix.x4.
// ---------------------------------------------------------------------------
#define LDMX4(R0, R1, R2, R3, ADDR)                                           \
    asm volatile("ldmatrix.sync.aligned.m8n8.x4.shared.b16 {%0,%1,%2,%3}, [%4];" \
                 : "=r"(R0), "=r"(R1), "=r"(R2), "=r"(R3) : "r"(ADDR))

#define MMA16816(D, A, B)                                                     \
    asm volatile("mma.sync.aligned.m16n8k16.row.col.f32.bf16.bf16.f32 "       \
                 "{%0,%1,%2,%3},{%4,%5,%6,%7},{%8,%9},{%0,%1,%2,%3};"          \
                 : "+f"(D[0]), "+f"(D[1]), "+f"(D[2]), "+f"(D[3])              \
                 : "r"(A[0]), "r"(A[1]), "r"(A[2]), "r"(A[3]),                 \
                   "r"(B[0]), "r"(B[1]))

__device__ __forceinline__ unsigned long long packkey(float v, int row) {
    unsigned ub = __float_as_uint(v);
    ub = (ub & 0x80000000u) ? ~ub : (ub | 0x80000000u);
    return ((unsigned long long)ub << 32) | (unsigned)(0xFFFFFFFFu - (unsigned)row);
}

__global__ void __launch_bounds__(256) k_mma(
    const __nv_bfloat16* __restrict__ Ah, const __nv_bfloat16* __restrict__ Al,
    const __nv_bfloat16* __restrict__ Bh, const __nv_bfloat16* __restrict__ Bl,
    int K, const float* __restrict__ bias,
    const float* __restrict__ addend, int ald,
    float* __restrict__ D, int do_argmax)
{
    constexpr int SROW = 40;   // bf16 elems per smem row slot (80B; conflict-free ldmatrix)
    __shared__ __align__(16) __nv_bfloat16 As[2][128 * SROW];
    __shared__ __align__(16) __nv_bfloat16 Bs[2][64 * SROW];
    __shared__ unsigned long long keys[64];

    const int tid  = threadIdx.x;
    const int lane = tid & 31;
    const int warp = tid >> 5;
    const int m0   = blockIdx.x * 128;
    const int mw   = warp * 16;
    if (do_argmax && tid < 64) keys[tid] = 0ULL;

    float acc[8][4];
#pragma unroll
    for (int f = 0; f < 8; f++)
#pragma unroll
        for (int j = 0; j < 4; j++) acc[f][j] = 0.f;

    // ldmatrix per-lane address components
    const int a_row  = mw + ((lane >> 3) & 1) * 8 + (lane & 7);
    const int a_koff = (lane >> 4) * 8;
    const int b_row  = (lane >> 4) * 8 + (lane & 7);
    const int b_koff = ((lane >> 3) & 1) * 8;

    for (int k0 = 0; k0 < K; k0 += 32) {
        // stage A slab: 128 rows x 32 bf16 x 2 splits
#pragma unroll
        for (int i = 0; i < 2; i++) {
            int id = tid + i * 256;
            int r = id >> 2, c = id & 3;
            *(float4*)(&As[0][r * SROW + c * 8]) =
                *(const float4*)(Ah + (size_t)(m0 + r) * K + k0 + c * 8);
            *(float4*)(&As[1][r * SROW + c * 8]) =
                *(const float4*)(Al + (size_t)(m0 + r) * K + k0 + c * 8);
        }
        // stage B slab: 64 rows x 32 bf16 x 2 splits
        {
            int r = tid >> 2, c = tid & 3;
            *(float4*)(&Bs[0][r * SROW + c * 8]) =
                *(const float4*)(Bh + (size_t)r * K + k0 + c * 8);
            *(float4*)(&Bs[1][r * SROW + c * 8]) =
                *(const float4*)(Bl + (size_t)r * K + k0 + c * 8);
        }
        __syncthreads();

#pragma unroll
        for (int ks = 0; ks < 2; ks++) {
            const int kk = ks * 16;
            uint32_t ah[4], al[4];
            {
                uint32_t ad = (uint32_t)__cvta_generic_to_shared(
                    &As[0][a_row * SROW + kk + a_koff]);
                LDMX4(ah[0], ah[1], ah[2], ah[3], ad);
                ad = (uint32_t)__cvta_generic_to_shared(
                    &As[1][a_row * SROW + kk + a_koff]);
                LDMX4(al[0], al[1], al[2], al[3], ad);
            }
            uint32_t bh[8][2], bl[8][2];
#pragma unroll
            for (int p = 0; p < 4; p++) {
                uint32_t ad = (uint32_t)__cvta_generic_to_shared(
                    &Bs[0][(p * 16 + b_row) * SROW + kk + b_koff]);
                LDMX4(bh[2 * p][0], bh[2 * p][1], bh[2 * p + 1][0], bh[2 * p + 1][1], ad);
                ad = (uint32_t)__cvta_generic_to_shared(
                    &Bs[1][(p * 16 + b_row) * SROW + kk + b_koff]);
                LDMX4(bl[2 * p][0], bl[2 * p][1], bl[2 * p + 1][0], bl[2 * p + 1][1], ad);
            }
#pragma unroll
            for (int f = 0; f < 8; f++) {
                MMA16816(acc[f], ah, bh[f]);
                MMA16816(acc[f], ah, bl[f]);
                MMA16816(acc[f], al, bh[f]);
            }
        }
        __syncthreads();
    }

    const int g  = lane >> 2;
    const int tq = lane & 3;
    const int r0 = m0 + mw + g;
    const int r1 = r0 + 8;

    if (!do_argmax) {
        float b0v = bias ? bias[r0] : 0.f;
        float b1v = bias ? bias[r1] : 0.f;
#pragma unroll
        for (int f = 0; f < 8; f++) {
#pragma unroll
            for (int j = 0; j < 2; j++) {
                int c = f * 8 + tq * 2 + j;
                float a0 = addend ? addend[(size_t)c * ald + r0] : 0.f;
                float a1 = addend ? addend[(size_t)c * ald + r1] : 0.f;
                D[(size_t)r0 * 64 + c] = acc[f][j] + b0v + a0;
                D[(size_t)r1 * 64 + c] = acc[f][2 + j] + b1v + a1;
            }
        }
    } else {
        const float b0v = bias[r0];
        const float b1v = bias[r1];
        unsigned long long kk2[16];
#pragma unroll
        for (int f = 0; f < 8; f++) {
#pragma unroll
            for (int j = 0; j < 2; j++) {
                unsigned long long u0 = packkey(acc[f][j] + b0v, r0);
                unsigned long long u1 = packkey(acc[f][2 + j] + b1v, r1);
                kk2[f * 2 + j] = (u0 > u1) ? u0 : u1;
            }
        }
        // reduce over the 8 lanes that share (lane&3): xor strides 4, 8, 16
#pragma unroll
        for (int s = 4; s <= 16; s <<= 1) {
#pragma unroll
            for (int q = 0; q < 16; q++) {
                unsigned long long o = __shfl_xor_sync(0xffffffffu, kk2[q], s);
                if (o > kk2[q]) kk2[q] = o;
            }
        }
        if (lane < 4) {
#pragma unroll
            for (int f = 0; f < 8; f++)
#pragma unroll
                for (int j = 0; j < 2; j++)
                    atomicMax(&keys[f * 8 + lane * 2 + j], kk2[f * 2 + j]);
        }
        __syncthreads();
        if (tid < 64) atomicMax(&g_amax[tid], keys[tid]);
    }
}

// ---------------------------------------------------------------------------
// GRU gates on transposed gi/gh; writes h (fp32) + bf16 split
// ---------------------------------------------------------------------------
__global__ void k_gates2() {
    int idx = blockIdx.x * blockDim.x + threadIdx.x;
    if (idx >= B_ * H_) return;
    int b = idx & (B_ - 1);
    int i = idx >> 6;
    float ir = g_giT[(size_t)i * 64 + b];
    float iz = g_giT[(size_t)(H_ + i) * 64 + b];
    float in_ = g_giT[(size_t)(2 * H_ + i) * 64 + b];
    float hr = g_ghT[(size_t)i * 64 + b];
    float hz = g_ghT[(size_t)(H_ + i) * 64 + b];
    float hn = g_ghT[(size_t)(2 * H_ + i) * 64 + b];
    float r = 1.f / (1.f + expf(-(ir + hr)));
    float z = 1.f / (1.f + expf(-(iz + hz)));
    float n = tanhf(in_ + r * hn);
    size_t hidx = (size_t)b * H_ + i;
    float h = g_h[hidx];
    float hnew = (1.f - z) * n + z * h;
    g_h[hidx] = hnew;
    __nv_bfloat16 hh = __float2bfloat16(hnew);
    g_h_hi[hidx] = hh;
    g_h_lo[hidx] = __float2bfloat16(hnew - __bfloat162float(hh));
}

// ---------------------------------------------------------------------------
__global__ void k_token(float* __restrict__ out_tok, int t) {
    int b = threadIdx.x;
    if (b >= B_) return;
    unsigned long long key = g_amax[b];
    int tok = (int)(0xFFFFFFFFu - (unsigned)(key & 0xFFFFFFFFull));
    out_tok[b * T_ + t] = (float)tok;
    int fin = g_fin[b] | (tok == EOS);
    g_fin[b] = fin;
    g_inp[b] = fin ? EOS : tok;
}

__global__ void k_writeh(float* __restrict__ out_h) {
    int idx = blockIdx.x * blockDim.x + threadIdx.x;
    if (idx < B_ * H_) out_h[idx] = g_h[idx];
}

// ---------------------------------------------------------------------------
extern "C" void kernel_launch(void* const* d_in, const int* in_sizes, int n_in,
                              void* d_out, int out_size) {
    const float* enc   = (const float*)d_in[0];
    const float* emb   = (const float*)d_in[1];
    const float* Wh_w  = (const float*)d_in[2];
    const float* Wh_b  = (const float*)d_in[3];
    const float* W_ih  = (const float*)d_in[4];
    const float* W_hh  = (const float*)d_in[5];
    const float* b_ih  = (const float*)d_in[6];
    const float* b_hh  = (const float*)d_in[7];
    const float* out_w = (const float*)d_in[8];
    const float* out_b = (const float*)d_in[9];
    float* out = (float*)d_out;

    void *pv;
    cudaGetSymbolAddress(&pv, g_flat);     float* f_flat = (float*)pv;
    cudaGetSymbolAddress(&pv, g_h);        float* f_h    = (float*)pv;
    cudaGetSymbolAddress(&pv, g_Gc);       float* f_Gc   = (float*)pv;
    cudaGetSymbolAddress(&pv, g_giT);      float* f_giT  = (float*)pv;
    cudaGetSymbolAddress(&pv, g_ghT);      float* f_ghT  = (float*)pv;
    cudaGetSymbolAddress(&pv, g_WihE_hi);  __nv_bfloat16* w_ihe_h = (__nv_bfloat16*)pv;
    cudaGetSymbolAddress(&pv, g_WihE_lo);  __nv_bfloat16* w_ihe_l = (__nv_bfloat16*)pv;
    cudaGetSymbolAddress(&pv, g_Whh_hi);   __nv_bfloat16* w_hh_h  = (__nv_bfloat16*)pv;
    cudaGetSymbolAddress(&pv, g_Whh_lo);   __nv_bfloat16* w_hh_l  = (__nv_bfloat16*)pv;
    cudaGetSymbolAddress(&pv, g_Wout_hi);  __nv_bfloat16* w_o_h   = (__nv_bfloat16*)pv;
    cudaGetSymbolAddress(&pv, g_Wout_lo);  __nv_bfloat16* w_o_l   = (__nv_bfloat16*)pv;
    cudaGetSymbolAddress(&pv, g_x_hi);     __nv_bfloat16* x_h     = (__nv_bfloat16*)pv;
    cudaGetSymbolAddress(&pv, g_x_lo);     __nv_bfloat16* x_l     = (__nv_bfloat16*)pv;
    cudaGetSymbolAddress(&pv, g_h_hi);     __nv_bfloat16* h_hi    = (__nv_bfloat16*)pv;
    cudaGetSymbolAddress(&pv, g_h_lo);     __nv_bfloat16* h_lo    = (__nv_bfloat16*)pv;

    // ---- one-time setup ----
    k_setup<<<256, 256>>>(enc);
    // h0 = flat @ Wh_w^T + Wh_b
    k_gemm<<<H_ / 64, 256>>>(f_flat, 2 * HENC, Wh_w, 2 * HENC, 0, 2 * HENC, Wh_b, f_h, H_);
    // Gc = context @ W_ih[:, E:]^T + b_ih
    k_gemm<<<3 * H_ / 64, 256>>>(f_flat, 2 * HENC, W_ih, E_ + 2 * HENC, E_, 2 * HENC,
                                 b_ih, f_Gc, 3 * H_);
    k_split_h0<<<(B_ * H_) / 256, 256>>>();
    // weight splits
    k_splitw<<<(3 * H_ * E_) / 256, 256>>>(W_ih, E_ + 2 * HENC, 0, E_,
                                           w_ihe_h, w_ihe_l, 3 * H_ * E_);
    k_splitw<<<(3 * H_ * H_) / 256, 256>>>(W_hh, H_, 0, H_,
                                           w_hh_h, w_hh_l, 3 * H_ * H_);
    k_splitw<<<(V_ * H_) / 256, 256>>>(out_w, H_, 0, H_,
                                       w_o_h, w_o_l, V_ * H_);

    // ---- decode loop ----
    for (int t = 0; t < T_; t++) {
        k_split_x<<<(B_ * E_) / 256, 256>>>(emb);
        // gi^T = W_ihE @ x^T (+ Gc^T)
        k_mma<<<3 * H_ / 128, 256>>>(w_ihe_h, w_ihe_l, x_h, x_l, E_,
                                     nullptr, f_Gc, 3 * H_, f_giT, 0);
        // gh^T = W_hh @ h^T + b_hh
        k_mma<<<3 * H_ / 128, 256>>>(w_hh_h, w_hh_l, h_hi, h_lo, H_,
                                     b_hh, nullptr, 0, f_ghT, 0);
        k_gates2<<<(B_ * H_) / 256, 256>>>();
        // logits + fused argmax
        k_mma<<<V_ / 128, 256>>>(w_o_h, w_o_l, h_hi, h_lo, H_,
                                 out_b, nullptr, 0, nullptr, 1);
        k_token<<<1, 64>>>(out, t);
    }

    if (out_size >= B_ * T_ + B_ * H_)
        k_writeh<<<(B_ * H_) / 256, 256>>>(out + B_ * T_);
}

// round 7
// speedup vs baseline: 2.4935x; 2.1519x over previous
#include <cuda_runtime.h>
#include <cuda_bf16.h>
#include <math.h>
#include <stdint.h>

static constexpr int B_   = 64;
static constexpr int HENC = 512;
static constexpr int E_   = 512;
static constexpr int H_   = 1024;
static constexpr int V_   = 32000;
static constexpr int T_   = 64;
static constexpr int SOS  = 1;
static constexpr int EOS  = 2;

// ---------------- persistent device state ----------------
__device__ float g_flat[B_ * 2 * HENC];
__device__ float g_h[B_ * H_];
__device__ float g_Gc[B_ * 3 * H_];          // [64][3072] context part of gi (incl b_ih)
__device__ float g_GcT[3 * H_ * B_];         // [3072][64] transposed addend
__device__ float g_giT[3 * H_ * B_];         // [3072][64]
__device__ float g_ghT[3 * H_ * B_];
__device__ int   g_inp[B_];
__device__ int   g_fin[B_];
__device__ unsigned long long g_amax[B_];

// bf16 split weights / activations
__device__ __nv_bfloat16 g_WihE_hi[3 * H_ * E_];
__device__ __nv_bfloat16 g_WihE_lo[3 * H_ * E_];
__device__ __nv_bfloat16 g_Whh_hi[3 * H_ * H_];
__device__ __nv_bfloat16 g_Whh_lo[3 * H_ * H_];
__device__ __nv_bfloat16 g_Wout_hi[(size_t)V_ * H_];
__device__ __nv_bfloat16 g_Wout_lo[(size_t)V_ * H_];
__device__ __nv_bfloat16 g_x_hi[B_ * E_];
__device__ __nv_bfloat16 g_x_lo[B_ * E_];
__device__ __nv_bfloat16 g_h_hi[B_ * H_];
__device__ __nv_bfloat16 g_h_lo[B_ * H_];

// ---------------------------------------------------------------------------
__device__ __forceinline__ uint32_t smem_u32(const void* p) {
    uint32_t a;
    asm("{ .reg .u64 t; cvta.to.shared.u64 t, %1; cvt.u32.u64 %0, t; }"
        : "=r"(a) : "l"(p));
    return a;
}

#define CP16(dst, src)                                                        \
    asm volatile("cp.async.cg.shared.global [%0], [%1], 16;"                  \
                 :: "r"(dst), "l"(src))
#define CP_COMMIT() asm volatile("cp.async.commit_group;")
#define CP_WAIT(n)  asm volatile("cp.async.wait_group %0;" :: "n"(n))

#define LDMX4(R0, R1, R2, R3, ADDR)                                           \
    asm volatile("ldmatrix.sync.aligned.m8n8.x4.shared.b16 {%0,%1,%2,%3}, [%4];" \
                 : "=r"(R0), "=r"(R1), "=r"(R2), "=r"(R3) : "r"(ADDR))

#define MMA16816(D, A, Bv)                                                    \
    asm volatile("mma.sync.aligned.m16n8k16.row.col.f32.bf16.bf16.f32 "       \
                 "{%0,%1,%2,%3},{%4,%5,%6,%7},{%8,%9},{%0,%1,%2,%3};"          \
                 : "+f"(D[0]), "+f"(D[1]), "+f"(D[2]), "+f"(D[3])              \
                 : "r"(A[0]), "r"(A[1]), "r"(A[2]), "r"(A[3]),                 \
                   "r"(Bv[0]), "r"(Bv[1]))

__device__ __forceinline__ unsigned long long packkey(float v, int row) {
    unsigned ub = __float_as_uint(v);
    ub = (ub & 0x80000000u) ? ~ub : (ub | 0x80000000u);
    return ((unsigned long long)ub << 32) | (unsigned)(0xFFFFFFFFu - (unsigned)row);
}

// ---------------------------------------------------------------------------
// smem layout for the MMA kernels (dynamic, double-buffered)
//   A: buf(2) x split(2) x 128 rows x 40 bf16 (80B stride; 64B payload)
//   B: buf(2) x split(2) x  64 rows x 40 bf16
// ---------------------------------------------------------------------------
static constexpr int SROW = 40;
__device__ __forceinline__ uint32_t abuf_off(int buf, int split) {
    return (uint32_t)(buf * 20480 + split * 10240);
}
__device__ __forceinline__ uint32_t bbuf_off(int buf, int split) {
    return (uint32_t)(40960 + buf * 10240 + split * 5120);
}
static constexpr int KEYS_OFF = 61440;
static constexpr int TCSMEM   = 61952;

// ---------------------------------------------------------------------------
// Core split-bf16 GEMM: D[M,64] = (Ah+Al)[M,K] @ (Bh+Bl)[64,K]^T
// (3 products hh+hl+lh). 128x64 tile per CTA, 8 warps, cp.async 2-stage.
// ARGMAX=0: D[r*64+c] = acc + bias[r] + addT[r*64+c]
// ARGMAX=1: fused per-batch argmax into g_amax (logits)
// ---------------------------------------------------------------------------
template <int ARGMAX>
__device__ __forceinline__ void mma_core(
    const __nv_bfloat16* __restrict__ Ah, const __nv_bfloat16* __restrict__ Al,
    const __nv_bfloat16* __restrict__ Bh, const __nv_bfloat16* __restrict__ Bl,
    int K, const float* __restrict__ bias, const float* __restrict__ addT,
    float* __restrict__ D, int m0)
{
    extern __shared__ __align__(16) char smem[];
    const uint32_t sb = smem_u32(smem);
    unsigned long long* keys = (unsigned long long*)(smem + KEYS_OFF);
    const int tid = threadIdx.x, lane = tid & 31, warp = tid >> 5;
    const int mw = warp * 16;
    if (ARGMAX && tid < 64) keys[tid] = 0ULL;

    float acc[8][4];
#pragma unroll
    for (int f = 0; f < 8; f++)
#pragma unroll
        for (int j = 0; j < 4; j++) acc[f][j] = 0.f;

    const int a_row  = mw + ((lane >> 3) & 1) * 8 + (lane & 7);
    const int a_koff = (lane >> 4) * 8;
    const int b_row  = (lane >> 4) * 8 + (lane & 7);
    const int b_koff = ((lane >> 3) & 1) * 8;

    const int nch = K >> 5;

    // ---- stage helper ----
    auto stage = [&](int kc, int buf) {
        const int kb = kc << 5;
#pragma unroll
        for (int i = 0; i < 2; i++) {
            int id = tid + (i << 8);
            int r = id >> 2, c = id & 3;
            uint32_t so = (uint32_t)(r * 80 + c * 16);
            const size_t go = (size_t)(m0 + r) * K + kb + c * 8;
            CP16(sb + abuf_off(buf, 0) + so, Ah + go);
            CP16(sb + abuf_off(buf, 1) + so, Al + go);
        }
        {
            int r = tid >> 2, c = tid & 3;
            uint32_t so = (uint32_t)(r * 80 + c * 16);
            const size_t go = (size_t)r * K + kb + c * 8;
            CP16(sb + bbuf_off(buf, 0) + so, Bh + go);
            CP16(sb + bbuf_off(buf, 1) + so, Bl + go);
        }
    };

    stage(0, 0);
    CP_COMMIT();

    for (int kc = 0; kc < nch; kc++) {
        const int cur = kc & 1;
        if (kc + 1 < nch) {
            stage(kc + 1, cur ^ 1);
            CP_COMMIT();
            CP_WAIT(1);
        } else {
            CP_WAIT(0);
        }
        __syncthreads();

#pragma unroll
        for (int ks = 0; ks < 2; ks++) {
            const int kk = ks * 16;
            uint32_t ah[4], al[4];
            {
                uint32_t ad = sb + abuf_off(cur, 0) +
                              (uint32_t)((a_row * SROW + kk + a_koff) * 2);
                LDMX4(ah[0], ah[1], ah[2], ah[3], ad);
                ad = sb + abuf_off(cur, 1) +
                     (uint32_t)((a_row * SROW + kk + a_koff) * 2);
                LDMX4(al[0], al[1], al[2], al[3], ad);
            }
            uint32_t bh[8][2], bl[8][2];
#pragma unroll
            for (int p = 0; p < 4; p++) {
                uint32_t ad = sb + bbuf_off(cur, 0) +
                              (uint32_t)(((p * 16 + b_row) * SROW + kk + b_koff) * 2);
                LDMX4(bh[2 * p][0], bh[2 * p][1], bh[2 * p + 1][0], bh[2 * p + 1][1], ad);
                ad = sb + bbuf_off(cur, 1) +
                     (uint32_t)(((p * 16 + b_row) * SROW + kk + b_koff) * 2);
                LDMX4(bl[2 * p][0], bl[2 * p][1], bl[2 * p + 1][0], bl[2 * p + 1][1], ad);
            }
#pragma unroll
            for (int f = 0; f < 8; f++) {
                MMA16816(acc[f], ah, bh[f]);
                MMA16816(acc[f], ah, bl[f]);
                MMA16816(acc[f], al, bh[f]);
            }
        }
        __syncthreads();
    }

    const int g  = lane >> 2;
    const int tq = lane & 3;
    const int r0 = m0 + mw + g;
    const int r1 = r0 + 8;

    if (!ARGMAX) {
        const float b0v = bias ? bias[r0] : 0.f;
        const float b1v = bias ? bias[r1] : 0.f;
#pragma unroll
        for (int f = 0; f < 8; f++) {
#pragma unroll
            for (int j = 0; j < 2; j++) {
                const int c = f * 8 + tq * 2 + j;
                float v0 = acc[f][j]     + b0v;
                float v1 = acc[f][2 + j] + b1v;
                if (addT) {
                    v0 += addT[(size_t)r0 * 64 + c];
                    v1 += addT[(size_t)r1 * 64 + c];
                }
                D[(size_t)r0 * 64 + c] = v0;
                D[(size_t)r1 * 64 + c] = v1;
            }
        }
    } else {
        const float b0v = bias[r0];
        const float b1v = bias[r1];
        unsigned long long kk2[16];
#pragma unroll
        for (int f = 0; f < 8; f++) {
#pragma unroll
            for (int j = 0; j < 2; j++) {
                unsigned long long u0 = packkey(acc[f][j]     + b0v, r0);
                unsigned long long u1 = packkey(acc[f][2 + j] + b1v, r1);
                kk2[f * 2 + j] = (u0 > u1) ? u0 : u1;
            }
        }
#pragma unroll
        for (int s = 4; s <= 16; s <<= 1) {
#pragma unroll
            for (int q = 0; q < 16; q++) {
                unsigned long long o = __shfl_xor_sync(0xffffffffu, kk2[q], s);
                if (o > kk2[q]) kk2[q] = o;
            }
        }
        if (lane < 4) {
#pragma unroll
            for (int f = 0; f < 8; f++)
#pragma unroll
                for (int j = 0; j < 2; j++)
                    atomicMax(&keys[f * 8 + lane * 2 + j], kk2[f * 2 + j]);
        }
        __syncthreads();
        if (tid < 64) atomicMax(&g_amax[tid], keys[tid]);
    }
}

// gi (y=0): W_ihE @ x^T + GcT ;  gh (y=1): W_hh @ h^T + b_hh
__global__ void __launch_bounds__(256) k_tc_gates(const float* __restrict__ b_hh) {
    const int m0 = blockIdx.x * 128;
    if (blockIdx.y == 0)
        mma_core<0>(g_WihE_hi, g_WihE_lo, g_x_hi, g_x_lo, E_,
                    nullptr, g_GcT, g_giT, m0);
    else
        mma_core<0>(g_Whh_hi, g_Whh_lo, g_h_hi, g_h_lo, H_,
                    b_hh, nullptr, g_ghT, m0);
}

__global__ void __launch_bounds__(256) k_tc_logits(const float* __restrict__ out_b) {
    mma_core<1>(g_Wout_hi, g_Wout_lo, g_h_hi, g_h_lo, H_,
                out_b, nullptr, nullptr, blockIdx.x * 128);
}

// ---------------------------------------------------------------------------
__global__ void k_setup(const float* __restrict__ enc) {
    int idx = blockIdx.x * blockDim.x + threadIdx.x;
    if (idx < B_ * 2 * HENC) {
        int b = idx / (2 * HENC);
        int k = idx % (2 * HENC);
        float v = (k < HENC) ? enc[b * HENC + k]
                             : enc[B_ * HENC + b * HENC + (k - HENC)];
        g_flat[idx] = v;
    }
    if (idx < B_) { g_inp[idx] = SOS; g_fin[idx] = 0; }
}

// fp32 GEMM (one-time: h0, Gc). C[64,N] = A[64,K] @ W[N,K]^T + bias
__global__ void __launch_bounds__(256) k_gemm(
    const float* __restrict__ A, int lda,
    const float* __restrict__ W, int ldw, int woff, int K,
    const float* __restrict__ bias, float* __restrict__ C, int ldc)
{
    __shared__ float As[32][68];
    __shared__ float Ws[32][68];
    const int tid = threadIdx.x;
    const int tx = tid & 15, ty = tid >> 4;
    const int n0 = blockIdx.x * 64;
    float acc[4][4] = {};

    for (int k0 = 0; k0 < K; k0 += 32) {
#pragma unroll
        for (int it = 0; it < 2; it++) {
            int idx = tid + it * 256;
            int row = idx >> 3;
            int kq  = (idx & 7) << 2;
            float4 v = *(const float4*)(A + (size_t)row * lda + k0 + kq);
            As[kq][row] = v.x; As[kq + 1][row] = v.y;
            As[kq + 2][row] = v.z; As[kq + 3][row] = v.w;
            float4 u = *(const float4*)(W + (size_t)(n0 + row) * ldw + woff + k0 + kq);
            Ws[kq][row] = u.x; Ws[kq + 1][row] = u.y;
            Ws[kq + 2][row] = u.z; Ws[kq + 3][row] = u.w;
        }
        __syncthreads();
#pragma unroll
        for (int k = 0; k < 32; k++) {
            float4 a = *(const float4*)&As[k][ty << 2];
            float4 w = *(const float4*)&Ws[k][tx << 2];
            acc[0][0] += a.x * w.x; acc[0][1] += a.x * w.y; acc[0][2] += a.x * w.z; acc[0][3] += a.x * w.w;
            acc[1][0] += a.y * w.x; acc[1][1] += a.y * w.y; acc[1][2] += a.y * w.z; acc[1][3] += a.y * w.w;
            acc[2][0] += a.z * w.x; acc[2][1] += a.z * w.y; acc[2][2] += a.z * w.z; acc[2][3] += a.z * w.w;
            acc[3][0] += a.w * w.x; acc[3][1] += a.w * w.y; acc[3][2] += a.w * w.z; acc[3][3] += a.w * w.w;
        }
        __syncthreads();
    }
#pragma unroll
    for (int i = 0; i < 4; i++) {
        int row = (ty << 2) + i;
#pragma unroll
        for (int j = 0; j < 4; j++) {
            int col = n0 + (tx << 2) + j;
            float v = acc[i][j];
            if (bias) v += bias[col];
            C[(size_t)row * ldc + col] = v;
        }
    }
}

__global__ void k_splitw(const float* __restrict__ src, int ld, int coloff, int cols,
                         __nv_bfloat16* __restrict__ hi, __nv_bfloat16* __restrict__ lo,
                         int n)
{
    int idx = blockIdx.x * blockDim.x + threadIdx.x;
    if (idx >= n) return;
    int r = idx / cols, c = idx % cols;
    float v = src[(size_t)r * ld + coloff + c];
    __nv_bfloat16 h = __float2bfloat16(v);
    hi[idx] = h;
    lo[idx] = __float2bfloat16(v - __bfloat162float(h));
}

__global__ void k_split_h0() {
    int idx = blockIdx.x * blockDim.x + threadIdx.x;
    if (idx >= B_ * H_) return;
    float v = g_h[idx];
    __nv_bfloat16 h = __float2bfloat16(v);
    g_h_hi[idx] = h;
    g_h_lo[idx] = __float2bfloat16(v - __bfloat162float(h));
}

__global__ void k_mk_gcT() {
    int idx = blockIdx.x * blockDim.x + threadIdx.x;
    if (idx >= 3 * H_ * B_) return;
    int r = idx >> 6, c = idx & 63;
    g_GcT[idx] = g_Gc[(size_t)c * (3 * H_) + r];
}

__global__ void k_split_x(const float* __restrict__ emb) {
    int idx = blockIdx.x * blockDim.x + threadIdx.x;
    if (idx < B_) g_amax[idx] = 0ULL;
    if (idx >= B_ * E_) return;
    int b = idx >> 9;
    int k = idx & (E_ - 1);
    float v = emb[(size_t)g_inp[b] * E_ + k];
    __nv_bfloat16 h = __float2bfloat16(v);
    g_x_hi[idx] = h;
    g_x_lo[idx] = __float2bfloat16(v - __bfloat162float(h));
}

__global__ void k_gates2() {
    int idx = blockIdx.x * blockDim.x + threadIdx.x;
    if (idx >= B_ * H_) return;
    int b = idx & (B_ - 1);
    int i = idx >> 6;
    float ir  = g_giT[(size_t)i * 64 + b];
    float iz  = g_giT[(size_t)(H_ + i) * 64 + b];
    float in_ = g_giT[(size_t)(2 * H_ + i) * 64 + b];
    float hr  = g_ghT[(size_t)i * 64 + b];
    float hz  = g_ghT[(size_t)(H_ + i) * 64 + b];
    float hn  = g_ghT[(size_t)(2 * H_ + i) * 64 + b];
    float r = 1.f / (1.f + expf(-(ir + hr)));
    float z = 1.f / (1.f + expf(-(iz + hz)));
    float n = tanhf(in_ + r * hn);
    size_t hidx = (size_t)b * H_ + i;
    float h = g_h[hidx];
    float hnew = (1.f - z) * n + z * h;
    g_h[hidx] = hnew;
    __nv_bfloat16 hh = __float2bfloat16(hnew);
    g_h_hi[hidx] = hh;
    g_h_lo[hidx] = __float2bfloat16(hnew - __bfloat162float(hh));
}

__global__ void k_token(float* __restrict__ out_tok, int t) {
    int b = threadIdx.x;
    if (b >= B_) return;
    unsigned long long key = g_amax[b];
    int tok = (int)(0xFFFFFFFFu - (unsigned)(key & 0xFFFFFFFFull));
    out_tok[b * T_ + t] = (float)tok;
    int fin = g_fin[b] | (tok == EOS);
    g_fin[b] = fin;
    g_inp[b] = fin ? EOS : tok;
}

__global__ void k_writeh(float* __restrict__ out_h) {
    int idx = blockIdx.x * blockDim.x + threadIdx.x;
    if (idx < B_ * H_) out_h[idx] = g_h[idx];
}

// ---------------------------------------------------------------------------
extern "C" void kernel_launch(void* const* d_in, const int* in_sizes, int n_in,
                              void* d_out, int out_size) {
    const float* enc   = (const float*)d_in[0];
    const float* emb   = (const float*)d_in[1];
    const float* Wh_w  = (const float*)d_in[2];
    const float* Wh_b  = (const float*)d_in[3];
    const float* W_ih  = (const float*)d_in[4];
    const float* W_hh  = (const float*)d_in[5];
    const float* b_ih  = (const float*)d_in[6];
    const float* b_hh  = (const float*)d_in[7];
    const float* out_w = (const float*)d_in[8];
    const float* out_b = (const float*)d_in[9];
    float* out = (float*)d_out;

    void* pv;
    cudaGetSymbolAddress(&pv, g_flat);     float* f_flat = (float*)pv;
    cudaGetSymbolAddress(&pv, g_h);        float* f_h    = (float*)pv;
    cudaGetSymbolAddress(&pv, g_Gc);       float* f_Gc   = (float*)pv;
    cudaGetSymbolAddress(&pv, g_WihE_hi);  __nv_bfloat16* w_ihe_h = (__nv_bfloat16*)pv;
    cudaGetSymbolAddress(&pv, g_WihE_lo);  __nv_bfloat16* w_ihe_l = (__nv_bfloat16*)pv;
    cudaGetSymbolAddress(&pv, g_Whh_hi);   __nv_bfloat16* w_hh_h  = (__nv_bfloat16*)pv;
    cudaGetSymbolAddress(&pv, g_Whh_lo);   __nv_bfloat16* w_hh_l  = (__nv_bfloat16*)pv;
    cudaGetSymbolAddress(&pv, g_Wout_hi);  __nv_bfloat16* w_o_h   = (__nv_bfloat16*)pv;
    cudaGetSymbolAddress(&pv, g_Wout_lo);  __nv_bfloat16* w_o_l   = (__nv_bfloat16*)pv;

    cudaFuncSetAttribute(k_tc_gates,  cudaFuncAttributeMaxDynamicSharedMemorySize, TCSMEM);
    cudaFuncSetAttribute(k_tc_logits, cudaFuncAttributeMaxDynamicSharedMemorySize, TCSMEM);

    // ---- one-time setup ----
    k_setup<<<256, 256>>>(enc);
    k_gemm<<<H_ / 64, 256>>>(f_flat, 2 * HENC, Wh_w, 2 * HENC, 0, 2 * HENC, Wh_b, f_h, H_);
    k_gemm<<<3 * H_ / 64, 256>>>(f_flat, 2 * HENC, W_ih, E_ + 2 * HENC, E_, 2 * HENC,
                                 b_ih, f_Gc, 3 * H_);
    k_split_h0<<<(B_ * H_) / 256, 256>>>();
    k_mk_gcT<<<(3 * H_ * B_) / 256, 256>>>();
    k_splitw<<<(3 * H_ * E_) / 256, 256>>>(W_ih, E_ + 2 * HENC, 0, E_,
                                           w_ihe_h, w_ihe_l, 3 * H_ * E_);
    k_splitw<<<(3 * H_ * H_) / 256, 256>>>(W_hh, H_, 0, H_,
                                           w_hh_h, w_hh_l, 3 * H_ * H_);
    k_splitw<<<(V_ * H_) / 256, 256>>>(out_w, H_, 0, H_,
                                       w_o_h, w_o_l, V_ * H_);

    // ---- decode loop ----
    dim3 ggates(3 * H_ / 128, 2);
    for (int t = 0; t < T_; t++) {
        k_split_x<<<(B_ * E_) / 256, 256>>>(emb);
        k_tc_gates<<<ggates, 256, TCSMEM>>>(b_hh);
        k_gates2<<<(B_ * H_) / 256, 256>>>();
        k_tc_logits<<<V_ / 128, 256, TCSMEM>>>(out_b);
        k_token<<<1, 64>>>(out, t);
    }

    if (out_size >= B_ * T_ + B_ * H_)
        k_writeh<<<(B_ * H_) / 256, 256>>>(out + B_ * T_);
}